// round 13
// baseline (speedup 1.0000x reference)
#include <cuda_runtime.h>
#include <cuda_fp16.h>
#include <cstdint>

#define N_NODES 8192
#define N_EDGES 262144
#define D 512
#define MW 256   // 8192 bits / 32 = 256 mask words per row

// Scratch (device globals; no allocations allowed)
__device__ unsigned int g_mask[N_NODES * MW];           // 8 MB adjacency bitmask
__device__ float        g_dinv[N_NODES];                // D^{-1/2}
__device__ __align__(16) __half g_h[N_NODES * D];       // H = X@W (UNscaled), fp16
__device__ int          g_is64;                         // edge_index dtype flag
__device__ __align__(16) __half g_xh[N_NODES * D];      // fp16 X
__device__ __align__(16) __half g_wh[D * D];            // fp16 W

// ---------------------------------------------------------------------------
// 0) detect edge_index dtype (int64 vs int32): sample 512 odd int32 words.
// ---------------------------------------------------------------------------
__global__ void k_detect(const int* __restrict__ ei32) {
    int t = threadIdx.x;                   // 0..127
    const int4* p = (const int4*)ei32;
    int4 a = p[2 * t];
    int4 b = p[2 * t + 1];
    int nz = a.y | a.w | b.y | b.w;
    int any = __syncthreads_or(nz != 0);
    if (t == 0) g_is64 = any ? 0 : 1;
}

// ---------------------------------------------------------------------------
// 1) zero bitmask
// ---------------------------------------------------------------------------
__global__ void k_zero_mask() {
    int i = blockIdx.x * blockDim.x + threadIdx.x;
    if (i < N_NODES * MW / 4) ((uint4*)g_mask)[i] = make_uint4(0, 0, 0, 0);
}

// ---------------------------------------------------------------------------
// 2) symmetric edge scatter, 2 edges per thread
// ---------------------------------------------------------------------------
__global__ void k_scatter(const void* __restrict__ ei_raw) {
    int e2 = blockIdx.x * blockDim.x + threadIdx.x;
    if (e2 >= N_EDGES / 2) return;
    int u0, u1, v0, v1;
    if (g_is64) {
        const longlong2* pe = (const longlong2*)ei_raw;
        longlong2 uu = pe[e2];
        longlong2 vv = pe[N_EDGES / 2 + e2];
        u0 = (int)uu.x; u1 = (int)uu.y;
        v0 = (int)vv.x; v1 = (int)vv.y;
    } else {
        const int2* pe = (const int2*)ei_raw;
        int2 uu = pe[e2];
        int2 vv = pe[N_EDGES / 2 + e2];
        u0 = uu.x; u1 = uu.y;
        v0 = vv.x; v1 = vv.y;
    }
    u0 &= (N_NODES - 1); u1 &= (N_NODES - 1);
    v0 &= (N_NODES - 1); v1 &= (N_NODES - 1);
    atomicOr(&g_mask[u0 * MW + (v0 >> 5)], 1u << (v0 & 31));
    atomicOr(&g_mask[v0 * MW + (u0 >> 5)], 1u << (u0 & 31));
    atomicOr(&g_mask[u1 * MW + (v1 >> 5)], 1u << (v1 & 31));
    atomicOr(&g_mask[v1 * MW + (u1 >> 5)], 1u << (u1 & 31));
}

// ---------------------------------------------------------------------------
// 3) degree + dinv
// ---------------------------------------------------------------------------
__global__ void k_degree() {
    int row  = blockIdx.x * (blockDim.x >> 5) + (threadIdx.x >> 5);
    int lane = threadIdx.x & 31;
    if (row >= N_NODES) return;
    const uint4* m = (const uint4*)&g_mask[row * MW];
    int cnt = 0;
    #pragma unroll
    for (int w = 0; w < 2; w++) {
        uint4 q = m[lane + w * 32];
        cnt += __popc(q.x) + __popc(q.y) + __popc(q.z) + __popc(q.w);
    }
    #pragma unroll
    for (int o = 16; o; o >>= 1) cnt += __shfl_xor_sync(0xffffffffu, cnt, o);
    if (lane == 0) g_dinv[row] = rsqrtf((float)(cnt + 1));
}

// ---------------------------------------------------------------------------
// 3b) convert fp32 -> fp16 (8 floats / thread)
// ---------------------------------------------------------------------------
__global__ void k_cvt(const float4* __restrict__ src, uint4* __restrict__ dst, int n8) {
    int i = blockIdx.x * blockDim.x + threadIdx.x;
    if (i >= n8) return;
    float4 a = src[2 * i];
    float4 b = src[2 * i + 1];
    uint4 o;
    __half2 h;
    h = __floats2half2_rn(a.x, a.y); o.x = *(uint32_t*)&h;
    h = __floats2half2_rn(a.z, a.w); o.y = *(uint32_t*)&h;
    h = __floats2half2_rn(b.x, b.y); o.z = *(uint32_t*)&h;
    h = __floats2half2_rn(b.z, b.w); o.w = *(uint32_t*)&h;
    dst[i] = o;
}

// ---------------------------------------------------------------------------
// 4) Tensor-core GEMM (mma.sync fp16, fp32 acc), 4-stage cp.async pipeline.
//    R11 config: 128x128 CTA tile, 4 warps, 64x64 warp tile. Called per
//    column half (colOff = 0 or 256): grid (2,64) = 128 CTAs = one wave.
// ---------------------------------------------------------------------------
#define GBM 128
#define GBN 128
#define GBK 32
#define ASTRIDE 40    // halves: 32 + 8 pad
#define BSTRIDE 144   // halves: 128 + 16 pad
#define NSTAGE 4
#define A_BYTES (GBM * ASTRIDE * 2)          // 10240
#define B_BYTES (GBK * BSTRIDE * 2)          // 9216
#define STAGE_BYTES (A_BYTES + B_BYTES)      // 19456
#define SMEM_GEMM (NSTAGE * STAGE_BYTES)     // 77824
#define KTILES (D / GBK)                     // 16

__device__ __forceinline__ uint32_t smem_u32(const void* p) {
    uint32_t a;
    asm("{ .reg .u64 t; cvta.to.shared.u64 t, %1; cvt.u32.u64 %0, t; }" : "=r"(a) : "l"(p));
    return a;
}
__device__ __forceinline__ void cp16(uint32_t dst, const void* src) {
    asm volatile("cp.async.cg.shared.global [%0], [%1], 16;" :: "r"(dst), "l"(src) : "memory");
}
__device__ __forceinline__ void ldsm_x4(uint32_t* r, const void* p) {
    uint32_t a = (uint32_t)__cvta_generic_to_shared(p);
    asm volatile("ldmatrix.sync.aligned.m8n8.x4.shared.b16 {%0,%1,%2,%3}, [%4];"
                 : "=r"(r[0]), "=r"(r[1]), "=r"(r[2]), "=r"(r[3]) : "r"(a));
}
__device__ __forceinline__ void ldsm_x4t(uint32_t* r, const void* p) {
    uint32_t a = (uint32_t)__cvta_generic_to_shared(p);
    asm volatile("ldmatrix.sync.aligned.m8n8.x4.trans.shared.b16 {%0,%1,%2,%3}, [%4];"
                 : "=r"(r[0]), "=r"(r[1]), "=r"(r[2]), "=r"(r[3]) : "r"(a));
}
__device__ __forceinline__ void mma16816(float* c, const uint32_t* a, const uint32_t* b) {
    asm volatile("mma.sync.aligned.m16n8k16.row.col.f32.f16.f16.f32 "
                 "{%0,%1,%2,%3}, {%4,%5,%6,%7}, {%8,%9}, {%0,%1,%2,%3};"
                 : "+f"(c[0]), "+f"(c[1]), "+f"(c[2]), "+f"(c[3])
                 : "r"(a[0]), "r"(a[1]), "r"(a[2]), "r"(a[3]), "r"(b[0]), "r"(b[1]));
}

__global__ __launch_bounds__(128) void k_gemm_mma(int colOff) {
    extern __shared__ char dsm[];
    uint32_t sb = smem_u32(dsm);

    int tid  = threadIdx.x;            // 0..127
    int lane = tid & 31;
    int wid  = tid >> 5;               // 0..3
    int wm   = wid & 1;                // rows wm*64
    int wn   = wid >> 1;               // cols wn*64
    int rowBase = blockIdx.y * GBM;
    int colBase = colOff + blockIdx.x * GBN;

    float acc[4][8][4];
    #pragma unroll
    for (int mi = 0; mi < 4; mi++)
        #pragma unroll
        for (int ni = 0; ni < 8; ni++)
            #pragma unroll
            for (int q = 0; q < 4; q++) acc[mi][ni][q] = 0.0f;

    auto issue = [&](int t) {
        uint32_t base = sb + (t % NSTAGE) * STAGE_BYTES;
        #pragma unroll
        for (int k = 0; k < 4; k++) {              // A: 128x32 halves, 512 chunks
            int i = tid + k * 128;
            int r = i >> 2, cc = i & 3;
            cp16(base + r * 80 + cc * 16,
                 &g_xh[(rowBase + r) * D + t * GBK + cc * 8]);
        }
        #pragma unroll
        for (int k = 0; k < 4; k++) {              // B: 32x128 halves, 512 chunks
            int i = tid + k * 128;
            int r = i >> 4, cc = i & 15;
            cp16(base + A_BYTES + r * 288 + cc * 16,
                 &g_wh[(t * GBK + r) * D + colBase + cc * 8]);
        }
        asm volatile("cp.async.commit_group;" ::: "memory");
    };

    #pragma unroll
    for (int t = 0; t < NSTAGE - 1; t++) issue(t);

    for (int kt = 0; kt < KTILES; kt++) {
        __syncthreads();
        if (kt + NSTAGE - 1 < KTILES) issue(kt + NSTAGE - 1);
        else asm volatile("cp.async.commit_group;" ::: "memory");
        asm volatile("cp.async.wait_group %0;" :: "n"(NSTAGE - 1) : "memory");
        __syncthreads();

        const __half* Ah = (const __half*)(dsm + (kt % NSTAGE) * STAGE_BYTES);
        const __half* Bh = (const __half*)(dsm + (kt % NSTAGE) * STAGE_BYTES + A_BYTES);

        #pragma unroll
        for (int kk = 0; kk < GBK; kk += 16) {
            uint32_t af[4][4];
            #pragma unroll
            for (int mi = 0; mi < 4; mi++) {
                int r = wm * 64 + mi * 16 + (lane & 15);
                int c = kk + ((lane >> 4) << 3);
                ldsm_x4(af[mi], &Ah[r * ASTRIDE + c]);
            }
            uint32_t bf[8][2];
            #pragma unroll
            for (int np = 0; np < 4; np++) {
                int r = kk + (lane & 15);
                int c = wn * 64 + np * 16 + ((lane >> 4) << 3);
                uint32_t t4[4];
                ldsm_x4t(t4, &Bh[r * BSTRIDE + c]);
                bf[2 * np][0] = t4[0]; bf[2 * np][1] = t4[1];
                bf[2 * np + 1][0] = t4[2]; bf[2 * np + 1][1] = t4[3];
            }
            #pragma unroll
            for (int mi = 0; mi < 4; mi++)
                #pragma unroll
                for (int ni = 0; ni < 8; ni++)
                    mma16816(acc[mi][ni], af[mi], bf[ni]);
        }
    }

    // epilogue: write fp16 H (no scaling)
    int g  = lane >> 2;
    int tg = lane & 3;
    #pragma unroll
    for (int mi = 0; mi < 4; mi++) {
        int row0 = rowBase + wm * 64 + mi * 16 + g;
        int row1 = row0 + 8;
        #pragma unroll
        for (int ni = 0; ni < 8; ni++) {
            int col = colBase + wn * 64 + ni * 8 + tg * 2;
            __half2 v0 = __floats2half2_rn(acc[mi][ni][0], acc[mi][ni][1]);
            __half2 v1 = __floats2half2_rn(acc[mi][ni][2], acc[mi][ni][3]);
            *(__half2*)&g_h[row0 * D + col] = v0;
            *(__half2*)&g_h[row1 * D + col] = v1;
        }
    }
}

// ---------------------------------------------------------------------------
// 5) SpMM gather over ONE column half (256 cols = 32 uint4 of fp16):
//    out[i][half] = dinv_i*(sum_j dinv_j*H[j][half] + dinv_i*H[i][half]) + b
//    4 warps: warp q processes quarter q of the neighbor list across the full
//    32-uint4 width (1 uint4 per lane); warps combine via smem.
// ---------------------------------------------------------------------------
#define LIST_CAP 4096

__device__ __forceinline__ void fma_h8(float4& a, float4& b, uint4 u, float s) {
    float2 f;
    f = __half22float2(*(const __half2*)&u.x); a.x += s * f.x; a.y += s * f.y;
    f = __half22float2(*(const __half2*)&u.y); a.z += s * f.x; a.w += s * f.y;
    f = __half22float2(*(const __half2*)&u.z); b.x += s * f.x; b.y += s * f.y;
    f = __half22float2(*(const __half2*)&u.w); b.z += s * f.x; b.w += s * f.y;
}

__global__ __launch_bounds__(128) void k_spmm(const float* __restrict__ bias,
                                              float* __restrict__ out,
                                              int halfIdx) {
    __shared__ unsigned int smask[MW];
    __shared__ unsigned short list[LIST_CAP];
    __shared__ int wsum[4];
    __shared__ __align__(16) float part[3 * 32 * 8];   // 3 KB combine buffer

    int row  = blockIdx.x;
    int tid  = threadIdx.x;
    int lane = tid & 31;
    int wrp  = tid >> 5;

    smask[tid]       = g_mask[row * MW + tid];
    smask[tid + 128] = g_mask[row * MW + tid + 128];
    __syncthreads();

    unsigned int w0 = smask[2 * tid], w1 = smask[2 * tid + 1];
    int c = __popc(w0) + __popc(w1);
    int p = c;
    #pragma unroll
    for (int o = 1; o < 32; o <<= 1) {
        int t = __shfl_up_sync(0xffffffffu, p, o);
        if (lane >= o) p += t;
    }
    if (lane == 31) wsum[wrp] = p;
    __syncthreads();
    int wbase = 0;
    #pragma unroll
    for (int w = 0; w < 4; w++) wbase += (w < wrp) ? wsum[w] : 0;
    int total = wsum[0] + wsum[1] + wsum[2] + wsum[3];

    float dinv_i = rsqrtf((float)(total + 1));

    bool uselist = (total <= LIST_CAP);
    if (uselist) {
        int off = wbase + p - c;
        unsigned int bits = w0;
        int base = (2 * tid) << 5;
        while (bits) { int b = __ffs(bits) - 1; bits &= bits - 1; list[off++] = (unsigned short)(base + b); }
        bits = w1; base = (2 * tid + 1) << 5;
        while (bits) { int b = __ffs(bits) - 1; bits &= bits - 1; list[off++] = (unsigned short)(base + b); }
    }
    __syncthreads();

    const uint4* H4 = (const uint4*)g_h;   // 64 uint4 per 512-fp16 row
    int cb = halfIdx * 32 + lane;          // this thread's uint4 column

    float4 a0 = make_float4(0,0,0,0), b0 = make_float4(0,0,0,0);
    float4 a1 = make_float4(0,0,0,0), b1 = make_float4(0,0,0,0);
    float4 a2 = make_float4(0,0,0,0), b2 = make_float4(0,0,0,0);
    float4 a3 = make_float4(0,0,0,0), b3 = make_float4(0,0,0,0);

    if (wrp == 0) fma_h8(a0, b0, H4[row * 64 + cb], dinv_i);   // identity

    if (uselist) {
        int per = total >> 2;
        int lo = wrp * per;
        int hi = (wrp == 3) ? total : lo + per;
        int i = lo;
        for (; i + 4 <= hi; i += 4) {
            int j0 = list[i], j1 = list[i + 1], j2 = list[i + 2], j3 = list[i + 3];
            float s0v = g_dinv[j0], s1v = g_dinv[j1], s2v = g_dinv[j2], s3v = g_dinv[j3];
            uint4 u0 = H4[j0 * 64 + cb];
            uint4 u1 = H4[j1 * 64 + cb];
            uint4 u2 = H4[j2 * 64 + cb];
            uint4 u3 = H4[j3 * 64 + cb];
            fma_h8(a0, b0, u0, s0v);
            fma_h8(a1, b1, u1, s1v);
            fma_h8(a2, b2, u2, s2v);
            fma_h8(a3, b3, u3, s3v);
        }
        for (; i < hi; i++) {
            int j = list[i];
            fma_h8(a0, b0, H4[j * 64 + cb], g_dinv[j]);
        }
    } else {
        for (int w = wrp * 64; w < wrp * 64 + 64; w++) {
            unsigned int bits = smask[w];
            while (bits) {
                int b = __ffs(bits) - 1;
                bits &= bits - 1;
                int j = (w << 5) + b;
                fma_h8(a0, b0, H4[j * 64 + cb], g_dinv[j]);
            }
        }
    }

    a0.x += a1.x + a2.x + a3.x;  a0.y += a1.y + a2.y + a3.y;
    a0.z += a1.z + a2.z + a3.z;  a0.w += a1.w + a2.w + a3.w;
    b0.x += b1.x + b2.x + b3.x;  b0.y += b1.y + b2.y + b3.y;
    b0.z += b1.z + b2.z + b3.z;  b0.w += b1.w + b2.w + b3.w;

    // combine warps via smem: warps 1-3 store, warp 0 reduces + writes
    if (wrp > 0) {
        ((float4*)part)[(wrp - 1) * 64 + lane * 2]     = a0;
        ((float4*)part)[(wrp - 1) * 64 + lane * 2 + 1] = b0;
    }
    __syncthreads();
    if (wrp == 0) {
        #pragma unroll
        for (int k = 0; k < 3; k++) {
            float4 pa = ((float4*)part)[k * 64 + lane * 2];
            float4 pb = ((float4*)part)[k * 64 + lane * 2 + 1];
            a0.x += pa.x; a0.y += pa.y; a0.z += pa.z; a0.w += pa.w;
            b0.x += pb.x; b0.y += pb.y; b0.z += pb.z; b0.w += pb.w;
        }
        int fo = halfIdx * 64 + lane * 2;   // float4 index within the row
        float4 bia = ((const float4*)bias)[fo];
        float4 bib = ((const float4*)bias)[fo + 1];
        float4 o0, o1;
        o0.x = dinv_i * a0.x + bia.x; o0.y = dinv_i * a0.y + bia.y;
        o0.z = dinv_i * a0.z + bia.z; o0.w = dinv_i * a0.w + bia.w;
        o1.x = dinv_i * b0.x + bib.x; o1.y = dinv_i * b0.y + bib.y;
        o1.z = dinv_i * b0.z + bib.z; o1.w = dinv_i * b0.w + bib.w;
        ((float4*)out)[row * (D / 4) + fo]     = o0;
        ((float4*)out)[row * (D / 4) + fo + 1] = o1;
    }
}

// ---------------------------------------------------------------------------
// launch: side stream: detect -> cvtX -> cvtW -> GEMM half0 -> GEMM half1;
// main stream: zero -> (wait detect) scatter -> degree ->
//              (wait GEMM0) SpMM half0 -> (wait GEMM1) SpMM half1.
// ---------------------------------------------------------------------------
extern "C" void kernel_launch(void* const* d_in, const int* in_sizes, int n_in,
                              void* d_out, int out_size) {
    const float* x    = (const float*)d_in[0];
    const void*  ei   = d_in[1];
    const float* w    = (const float*)d_in[2];
    const float* bias = (const float*)d_in[3];
    float*       out  = (float*)d_out;

    static cudaStream_t s2 = nullptr;
    static cudaEvent_t evFork = nullptr, evDet = nullptr, evG0 = nullptr, evG1 = nullptr;
    if (s2 == nullptr) {
        cudaStreamCreateWithFlags(&s2, cudaStreamNonBlocking);
        cudaEventCreateWithFlags(&evFork, cudaEventDisableTiming);
        cudaEventCreateWithFlags(&evDet, cudaEventDisableTiming);
        cudaEventCreateWithFlags(&evG0, cudaEventDisableTiming);
        cudaEventCreateWithFlags(&evG1, cudaEventDisableTiming);
        cudaFuncSetAttribute(k_gemm_mma, cudaFuncAttributeMaxDynamicSharedMemorySize,
                             SMEM_GEMM);
    }

    __half *xh, *wh;
    cudaGetSymbolAddress((void**)&xh, g_xh);
    cudaGetSymbolAddress((void**)&wh, g_wh);
    int nx8 = N_NODES * D / 8;
    int nw8 = D * D / 8;

    // fork
    cudaEventRecord(evFork, 0);
    cudaStreamWaitEvent(s2, evFork, 0);

    // side chain: detect -> converts -> GEMM halves
    k_detect<<<1, 128, 0, s2>>>((const int*)ei);
    cudaEventRecord(evDet, s2);
    k_cvt<<<(nx8 + 255) / 256, 256, 0, s2>>>((const float4*)x, (uint4*)xh, nx8);
    k_cvt<<<(nw8 + 255) / 256, 256, 0, s2>>>((const float4*)w, (uint4*)wh, nw8);
    dim3 gemmGrid(2, 64);   // 128 CTAs = one wave per half
    k_gemm_mma<<<gemmGrid, 128, SMEM_GEMM, s2>>>(0);
    cudaEventRecord(evG0, s2);
    k_gemm_mma<<<gemmGrid, 128, SMEM_GEMM, s2>>>(256);
    cudaEventRecord(evG1, s2);

    // main chain
    k_zero_mask<<<(N_NODES * MW / 4 + 255) / 256, 256>>>();
    cudaStreamWaitEvent(0, evDet, 0);
    k_scatter<<<(N_EDGES / 2 + 255) / 256, 256>>>(ei);
    k_degree<<<N_NODES / 8, 256>>>();

    // SpMM halves, each gated only on its GEMM half
    cudaStreamWaitEvent(0, evG0, 0);
    k_spmm<<<N_NODES, 128>>>(bias, out, 0);
    cudaStreamWaitEvent(0, evG1, 0);
    k_spmm<<<N_NODES, 128>>>(bias, out, 1);
}

// round 14
// speedup vs baseline: 1.3310x; 1.3310x over previous
#include <cuda_runtime.h>
#include <cuda_fp16.h>
#include <cstdint>

#define N_NODES 8192
#define N_EDGES 262144
#define D 512
#define MW 256   // 8192 bits / 32 = 256 mask words per row

// Scratch (device globals; no allocations allowed)
__device__ unsigned int g_mask[N_NODES * MW];           // 8 MB adjacency bitmask
__device__ float        g_dinv[N_NODES];                // D^{-1/2}
__device__ __align__(16) __half g_h[N_NODES * D];       // H = X@W (UNscaled), fp16
__device__ int          g_is64;                         // edge_index dtype flag
__device__ __align__(16) __half g_xh[N_NODES * D];      // fp16 X
__device__ __align__(16) __half g_wh[D * D];            // fp16 W

// ---------------------------------------------------------------------------
// 0) detect edge_index dtype (int64 vs int32): sample 512 odd int32 words.
// ---------------------------------------------------------------------------
__global__ void k_detect(const int* __restrict__ ei32) {
    int t = threadIdx.x;                   // 0..127
    const int4* p = (const int4*)ei32;
    int4 a = p[2 * t];
    int4 b = p[2 * t + 1];
    int nz = a.y | a.w | b.y | b.w;
    int any = __syncthreads_or(nz != 0);
    if (t == 0) g_is64 = any ? 0 : 1;
}

// ---------------------------------------------------------------------------
// 1) zero bitmask
// ---------------------------------------------------------------------------
__global__ void k_zero_mask() {
    int i = blockIdx.x * blockDim.x + threadIdx.x;
    if (i < N_NODES * MW / 4) ((uint4*)g_mask)[i] = make_uint4(0, 0, 0, 0);
}

// ---------------------------------------------------------------------------
// 2) symmetric edge scatter, 2 edges per thread
// ---------------------------------------------------------------------------
__global__ void k_scatter(const void* __restrict__ ei_raw) {
    int e2 = blockIdx.x * blockDim.x + threadIdx.x;
    if (e2 >= N_EDGES / 2) return;
    int u0, u1, v0, v1;
    if (g_is64) {
        const longlong2* pe = (const longlong2*)ei_raw;
        longlong2 uu = pe[e2];
        longlong2 vv = pe[N_EDGES / 2 + e2];
        u0 = (int)uu.x; u1 = (int)uu.y;
        v0 = (int)vv.x; v1 = (int)vv.y;
    } else {
        const int2* pe = (const int2*)ei_raw;
        int2 uu = pe[e2];
        int2 vv = pe[N_EDGES / 2 + e2];
        u0 = uu.x; u1 = uu.y;
        v0 = vv.x; v1 = vv.y;
    }
    u0 &= (N_NODES - 1); u1 &= (N_NODES - 1);
    v0 &= (N_NODES - 1); v1 &= (N_NODES - 1);
    atomicOr(&g_mask[u0 * MW + (v0 >> 5)], 1u << (v0 & 31));
    atomicOr(&g_mask[v0 * MW + (u0 >> 5)], 1u << (u0 & 31));
    atomicOr(&g_mask[u1 * MW + (v1 >> 5)], 1u << (v1 & 31));
    atomicOr(&g_mask[v1 * MW + (u1 >> 5)], 1u << (u1 & 31));
}

// ---------------------------------------------------------------------------
// 3) degree + dinv
// ---------------------------------------------------------------------------
__global__ void k_degree() {
    int row  = blockIdx.x * (blockDim.x >> 5) + (threadIdx.x >> 5);
    int lane = threadIdx.x & 31;
    if (row >= N_NODES) return;
    const uint4* m = (const uint4*)&g_mask[row * MW];
    int cnt = 0;
    #pragma unroll
    for (int w = 0; w < 2; w++) {
        uint4 q = m[lane + w * 32];
        cnt += __popc(q.x) + __popc(q.y) + __popc(q.z) + __popc(q.w);
    }
    #pragma unroll
    for (int o = 16; o; o >>= 1) cnt += __shfl_xor_sync(0xffffffffu, cnt, o);
    if (lane == 0) g_dinv[row] = rsqrtf((float)(cnt + 1));
}

// ---------------------------------------------------------------------------
// 3b) fused fp32 -> fp16 convert for X (blocks 0..2047) and W (2048..2175)
// ---------------------------------------------------------------------------
#define XBLOCKS 2048   // 8192*512/8 items / 256 thr
#define WBLOCKS 128    // 512*512/8 items / 256 thr

__global__ void k_cvt_xw(const float4* __restrict__ x, uint4* __restrict__ xh,
                         const float4* __restrict__ w, uint4* __restrict__ wh) {
    int b = blockIdx.x;
    const float4* src;
    uint4* dst;
    int i;
    if (b < XBLOCKS) {
        src = x; dst = xh;
        i = b * blockDim.x + threadIdx.x;
    } else {
        src = w; dst = wh;
        i = (b - XBLOCKS) * blockDim.x + threadIdx.x;
    }
    float4 a = src[2 * i];
    float4 c = src[2 * i + 1];
    uint4 o;
    __half2 h;
    h = __floats2half2_rn(a.x, a.y); o.x = *(uint32_t*)&h;
    h = __floats2half2_rn(a.z, a.w); o.y = *(uint32_t*)&h;
    h = __floats2half2_rn(c.x, c.y); o.z = *(uint32_t*)&h;
    h = __floats2half2_rn(c.z, c.w); o.w = *(uint32_t*)&h;
    dst[i] = o;
}

// ---------------------------------------------------------------------------
// 4) Tensor-core GEMM (mma.sync fp16, fp32 acc), 4-stage cp.async pipeline.
//    R11 config: 128x128 CTA tile, 4 warps, 64x64 warp tile, grid (4,64).
//    H[m][n] = sum_k X[m][k]*W[k][n] (fp16, unscaled; dinv applied in SpMM)
// ---------------------------------------------------------------------------
#define GBM 128
#define GBN 128
#define GBK 32
#define ASTRIDE 40    // halves: 32 + 8 pad
#define BSTRIDE 144   // halves: 128 + 16 pad
#define NSTAGE 4
#define A_BYTES (GBM * ASTRIDE * 2)          // 10240
#define B_BYTES (GBK * BSTRIDE * 2)          // 9216
#define STAGE_BYTES (A_BYTES + B_BYTES)      // 19456
#define SMEM_GEMM (NSTAGE * STAGE_BYTES)     // 77824
#define KTILES (D / GBK)                     // 16

__device__ __forceinline__ uint32_t smem_u32(const void* p) {
    uint32_t a;
    asm("{ .reg .u64 t; cvta.to.shared.u64 t, %1; cvt.u32.u64 %0, t; }" : "=r"(a) : "l"(p));
    return a;
}
__device__ __forceinline__ void cp16(uint32_t dst, const void* src) {
    asm volatile("cp.async.cg.shared.global [%0], [%1], 16;" :: "r"(dst), "l"(src) : "memory");
}
__device__ __forceinline__ void ldsm_x4(uint32_t* r, const void* p) {
    uint32_t a = (uint32_t)__cvta_generic_to_shared(p);
    asm volatile("ldmatrix.sync.aligned.m8n8.x4.shared.b16 {%0,%1,%2,%3}, [%4];"
                 : "=r"(r[0]), "=r"(r[1]), "=r"(r[2]), "=r"(r[3]) : "r"(a));
}
__device__ __forceinline__ void ldsm_x4t(uint32_t* r, const void* p) {
    uint32_t a = (uint32_t)__cvta_generic_to_shared(p);
    asm volatile("ldmatrix.sync.aligned.m8n8.x4.trans.shared.b16 {%0,%1,%2,%3}, [%4];"
                 : "=r"(r[0]), "=r"(r[1]), "=r"(r[2]), "=r"(r[3]) : "r"(a));
}
__device__ __forceinline__ void mma16816(float* c, const uint32_t* a, const uint32_t* b) {
    asm volatile("mma.sync.aligned.m16n8k16.row.col.f32.f16.f16.f32 "
                 "{%0,%1,%2,%3}, {%4,%5,%6,%7}, {%8,%9}, {%0,%1,%2,%3};"
                 : "+f"(c[0]), "+f"(c[1]), "+f"(c[2]), "+f"(c[3])
                 : "r"(a[0]), "r"(a[1]), "r"(a[2]), "r"(a[3]), "r"(b[0]), "r"(b[1]));
}

__global__ __launch_bounds__(128) void k_gemm_mma() {
    extern __shared__ char dsm[];
    uint32_t sb = smem_u32(dsm);

    int tid  = threadIdx.x;            // 0..127
    int lane = tid & 31;
    int wid  = tid >> 5;               // 0..3
    int wm   = wid & 1;                // rows wm*64
    int wn   = wid >> 1;               // cols wn*64
    int rowBase = blockIdx.y * GBM;
    int colBase = blockIdx.x * GBN;

    float acc[4][8][4];
    #pragma unroll
    for (int mi = 0; mi < 4; mi++)
        #pragma unroll
        for (int ni = 0; ni < 8; ni++)
            #pragma unroll
            for (int q = 0; q < 4; q++) acc[mi][ni][q] = 0.0f;

    auto issue = [&](int t) {
        uint32_t base = sb + (t % NSTAGE) * STAGE_BYTES;
        #pragma unroll
        for (int k = 0; k < 4; k++) {              // A: 128x32 halves, 512 chunks
            int i = tid + k * 128;
            int r = i >> 2, cc = i & 3;
            cp16(base + r * 80 + cc * 16,
                 &g_xh[(rowBase + r) * D + t * GBK + cc * 8]);
        }
        #pragma unroll
        for (int k = 0; k < 4; k++) {              // B: 32x128 halves, 512 chunks
            int i = tid + k * 128;
            int r = i >> 4, cc = i & 15;
            cp16(base + A_BYTES + r * 288 + cc * 16,
                 &g_wh[(t * GBK + r) * D + colBase + cc * 8]);
        }
        asm volatile("cp.async.commit_group;" ::: "memory");
    };

    #pragma unroll
    for (int t = 0; t < NSTAGE - 1; t++) issue(t);

    for (int kt = 0; kt < KTILES; kt++) {
        __syncthreads();
        if (kt + NSTAGE - 1 < KTILES) issue(kt + NSTAGE - 1);
        else asm volatile("cp.async.commit_group;" ::: "memory");
        asm volatile("cp.async.wait_group %0;" :: "n"(NSTAGE - 1) : "memory");
        __syncthreads();

        const __half* Ah = (const __half*)(dsm + (kt % NSTAGE) * STAGE_BYTES);
        const __half* Bh = (const __half*)(dsm + (kt % NSTAGE) * STAGE_BYTES + A_BYTES);

        #pragma unroll
        for (int kk = 0; kk < GBK; kk += 16) {
            uint32_t af[4][4];
            #pragma unroll
            for (int mi = 0; mi < 4; mi++) {
                int r = wm * 64 + mi * 16 + (lane & 15);
                int c = kk + ((lane >> 4) << 3);
                ldsm_x4(af[mi], &Ah[r * ASTRIDE + c]);
            }
            uint32_t bf[8][2];
            #pragma unroll
            for (int np = 0; np < 4; np++) {
                int r = kk + (lane & 15);
                int c = wn * 64 + np * 16 + ((lane >> 4) << 3);
                uint32_t t4[4];
                ldsm_x4t(t4, &Bh[r * BSTRIDE + c]);
                bf[2 * np][0] = t4[0]; bf[2 * np][1] = t4[1];
                bf[2 * np + 1][0] = t4[2]; bf[2 * np + 1][1] = t4[3];
            }
            #pragma unroll
            for (int mi = 0; mi < 4; mi++)
                #pragma unroll
                for (int ni = 0; ni < 8; ni++)
                    mma16816(acc[mi][ni], af[mi], bf[ni]);
        }
    }

    // epilogue: write fp16 H (no scaling)
    int g  = lane >> 2;
    int tg = lane & 3;
    #pragma unroll
    for (int mi = 0; mi < 4; mi++) {
        int row0 = rowBase + wm * 64 + mi * 16 + g;
        int row1 = row0 + 8;
        #pragma unroll
        for (int ni = 0; ni < 8; ni++) {
            int col = colBase + wn * 64 + ni * 8 + tg * 2;
            __half2 v0 = __floats2half2_rn(acc[mi][ni][0], acc[mi][ni][1]);
            __half2 v1 = __floats2half2_rn(acc[mi][ni][2], acc[mi][ni][3]);
            *(__half2*)&g_h[row0 * D + col] = v0;
            *(__half2*)&g_h[row1 * D + col] = v1;
        }
    }
}

// ---------------------------------------------------------------------------
// 5) SpMM gather (fp16 payload, 16B loads, per-neighbor dinv scaling)
// ---------------------------------------------------------------------------
#define LIST_CAP 4096

__device__ __forceinline__ void fma_h8(float4& a, float4& b, uint4 u, float s) {
    float2 f;
    f = __half22float2(*(const __half2*)&u.x); a.x += s * f.x; a.y += s * f.y;
    f = __half22float2(*(const __half2*)&u.y); a.z += s * f.x; a.w += s * f.y;
    f = __half22float2(*(const __half2*)&u.z); b.x += s * f.x; b.y += s * f.y;
    f = __half22float2(*(const __half2*)&u.w); b.z += s * f.x; b.w += s * f.y;
}

__global__ __launch_bounds__(128) void k_spmm(const float* __restrict__ bias,
                                              float* __restrict__ out) {
    __shared__ unsigned int smask[MW];
    __shared__ unsigned short list[LIST_CAP];
    __shared__ int wsum[4];
    __shared__ __align__(16) float part[64 * 8];

    int row  = blockIdx.x;
    int tid  = threadIdx.x;
    int lane = tid & 31;
    int wrp  = tid >> 5;

    smask[tid]       = g_mask[row * MW + tid];
    smask[tid + 128] = g_mask[row * MW + tid + 128];
    __syncthreads();

    unsigned int w0 = smask[2 * tid], w1 = smask[2 * tid + 1];
    int c = __popc(w0) + __popc(w1);
    int p = c;
    #pragma unroll
    for (int o = 1; o < 32; o <<= 1) {
        int t = __shfl_up_sync(0xffffffffu, p, o);
        if (lane >= o) p += t;
    }
    if (lane == 31) wsum[wrp] = p;
    __syncthreads();
    int wbase = 0;
    #pragma unroll
    for (int w = 0; w < 4; w++) wbase += (w < wrp) ? wsum[w] : 0;
    int total = wsum[0] + wsum[1] + wsum[2] + wsum[3];

    float dinv_i = rsqrtf((float)(total + 1));

    bool uselist = (total <= LIST_CAP);
    if (uselist) {
        int off = wbase + p - c;
        unsigned int bits = w0;
        int base = (2 * tid) << 5;
        while (bits) { int b = __ffs(bits) - 1; bits &= bits - 1; list[off++] = (unsigned short)(base + b); }
        bits = w1; base = (2 * tid + 1) << 5;
        while (bits) { int b = __ffs(bits) - 1; bits &= bits - 1; list[off++] = (unsigned short)(base + b); }
    }
    __syncthreads();

    int tid2 = tid & 63;
    int half = tid >> 6;

    const uint4* H4 = (const uint4*)g_h;

    float4 a0 = make_float4(0,0,0,0), b0 = make_float4(0,0,0,0);
    float4 a1 = make_float4(0,0,0,0), b1 = make_float4(0,0,0,0);
    float4 a2 = make_float4(0,0,0,0), b2 = make_float4(0,0,0,0);
    float4 a3 = make_float4(0,0,0,0), b3 = make_float4(0,0,0,0);

    if (half == 0) fma_h8(a0, b0, H4[row * 64 + tid2], dinv_i);   // identity

    if (uselist) {
        int mid = total >> 1;
        int lo = half ? mid : 0;
        int hi = half ? total : mid;
        int i = lo;
        for (; i + 4 <= hi; i += 4) {
            int j0 = list[i], j1 = list[i + 1], j2 = list[i + 2], j3 = list[i + 3];
            float s0v = g_dinv[j0], s1v = g_dinv[j1], s2v = g_dinv[j2], s3v = g_dinv[j3];
            uint4 u0 = H4[j0 * 64 + tid2];
            uint4 u1 = H4[j1 * 64 + tid2];
            uint4 u2 = H4[j2 * 64 + tid2];
            uint4 u3 = H4[j3 * 64 + tid2];
            fma_h8(a0, b0, u0, s0v);
            fma_h8(a1, b1, u1, s1v);
            fma_h8(a2, b2, u2, s2v);
            fma_h8(a3, b3, u3, s3v);
        }
        for (; i < hi; i++) {
            int j = list[i];
            fma_h8(a0, b0, H4[j * 64 + tid2], g_dinv[j]);
        }
    } else {
        for (int w = half * 128; w < half * 128 + 128; w++) {
            unsigned int bits = smask[w];
            while (bits) {
                int b = __ffs(bits) - 1;
                bits &= bits - 1;
                int j = (w << 5) + b;
                fma_h8(a0, b0, H4[j * 64 + tid2], g_dinv[j]);
            }
        }
    }

    a0.x += a1.x + a2.x + a3.x;  a0.y += a1.y + a2.y + a3.y;
    a0.z += a1.z + a2.z + a3.z;  a0.w += a1.w + a2.w + a3.w;
    b0.x += b1.x + b2.x + b3.x;  b0.y += b1.y + b2.y + b3.y;
    b0.z += b1.z + b2.z + b3.z;  b0.w += b1.w + b2.w + b3.w;

    if (half == 1) {
        ((float4*)part)[tid2 * 2]     = a0;
        ((float4*)part)[tid2 * 2 + 1] = b0;
    }
    __syncthreads();
    if (half == 0) {
        float4 pa = ((float4*)part)[tid2 * 2];
        float4 pb = ((float4*)part)[tid2 * 2 + 1];
        a0.x += pa.x; a0.y += pa.y; a0.z += pa.z; a0.w += pa.w;
        b0.x += pb.x; b0.y += pb.y; b0.z += pb.z; b0.w += pb.w;

        float4 bia = ((const float4*)bias)[tid2 * 2];
        float4 bib = ((const float4*)bias)[tid2 * 2 + 1];
        float4 o0, o1;
        o0.x = dinv_i * a0.x + bia.x; o0.y = dinv_i * a0.y + bia.y;
        o0.z = dinv_i * a0.z + bia.z; o0.w = dinv_i * a0.w + bia.w;
        o1.x = dinv_i * b0.x + bib.x; o1.y = dinv_i * b0.y + bib.y;
        o1.z = dinv_i * b0.z + bib.z; o1.w = dinv_i * b0.w + bib.w;
        ((float4*)out)[row * (D / 4) + tid2 * 2]     = o0;
        ((float4*)out)[row * (D / 4) + tid2 * 2 + 1] = o1;
    }
}

// ---------------------------------------------------------------------------
// launch:
//   stream0: detect -> zero -> scatter -> degree -> (wait evJoin) -> spmm
//   s2:      (wait evFork) cvt_xw -> gemm -> record evJoin
// ---------------------------------------------------------------------------
extern "C" void kernel_launch(void* const* d_in, const int* in_sizes, int n_in,
                              void* d_out, int out_size) {
    const float* x    = (const float*)d_in[0];
    const void*  ei   = d_in[1];
    const float* w    = (const float*)d_in[2];
    const float* bias = (const float*)d_in[3];
    float*       out  = (float*)d_out;

    static cudaStream_t s2 = nullptr;
    static cudaEvent_t evFork = nullptr, evJoin = nullptr;
    if (s2 == nullptr) {
        cudaStreamCreateWithFlags(&s2, cudaStreamNonBlocking);
        cudaEventCreateWithFlags(&evFork, cudaEventDisableTiming);
        cudaEventCreateWithFlags(&evJoin, cudaEventDisableTiming);
        cudaFuncSetAttribute(k_gemm_mma, cudaFuncAttributeMaxDynamicSharedMemorySize,
                             SMEM_GEMM);
    }

    __half *xh, *wh;
    cudaGetSymbolAddress((void**)&xh, g_xh);
    cudaGetSymbolAddress((void**)&wh, g_wh);

    // fork: side chain (cvt -> GEMM) is independent of the graph setup
    cudaEventRecord(evFork, 0);
    cudaStreamWaitEvent(s2, evFork, 0);

    k_cvt_xw<<<XBLOCKS + WBLOCKS, 256, 0, s2>>>((const float4*)x, (uint4*)xh,
                                                (const float4*)w, (uint4*)wh);
    dim3 gemmGrid(D / GBN, N_NODES / GBM);   // (4, 64) = 256 CTAs
    k_gemm_mma<<<gemmGrid, 128, SMEM_GEMM, s2>>>();
    cudaEventRecord(evJoin, s2);

    // main chain (detect feeds scatter on the same stream — no event needed)
    k_detect<<<1, 128>>>((const int*)ei);
    k_zero_mask<<<(N_NODES * MW / 4 + 255) / 256, 256>>>();
    k_scatter<<<(N_EDGES / 2 + 255) / 256, 256>>>(ei);
    k_degree<<<N_NODES / 8, 256>>>();

    // join, then SpMM
    cudaStreamWaitEvent(0, evJoin, 0);
    k_spmm<<<N_NODES, 128>>>(bias, out);
}